// round 16
// baseline (speedup 1.0000x reference)
#include <cuda_runtime.h>
#include <cuda_bf16.h>
#include <cstdint>

#define MAXN (1 << 21)            // >= N = 1,000,000
#define NBITS (1u << 29)          // keyspace: 8b batch | 7b x | 7b y | 7b z
#define NWORDS (NBITS / 32u)      // 16M u32 = 64MB
#define NGROUPS (NBITS / 128u)    // 4M groups of 128 bits
#define NSCANBLK (NGROUPS / 256u) // 16384 pass-1 blocks
#define COLL_CAP 32768
#define DUP_CAP  65536
#define KEYMASK 0x1fffffffu
#define ZBLOCKS 2048u             // bitmap-zero partition blocks in k67

__device__ uint32_t g_bitmap[NWORDS];   // all-zero between calls (k67 cleans)
__device__ uint32_t g_gprefix[NGROUPS];
__device__ uint32_t g_blksum[NSCANBLK];
__device__ uint32_t g_blkoff[NSCANBLK];
__device__ uint32_t g_numuniq;
__device__ uint32_t g_keys[MAXN];       // bit31 = "2nd+ inserter of its key"
__device__ uint32_t g_inv[MAXN];        // bit31 = dup flag, low = rank
__device__ uint32_t g_cid[MAXN];        // claim flag per rank; 0 between calls
__device__ uint32_t g_duplist[DUP_CAP];
__device__ uint32_t g_ranklist[COLL_CAP];
__device__ uint32_t g_ndup, g_nrank;

__device__ __forceinline__ uint32_t encf(float f) {
    uint32_t b = __float_as_uint(f);
    return (b & 0x80000000u) ? ~b : (b | 0x80000000u);
}
__device__ __forceinline__ float decf(uint32_t u) {
    return __uint_as_float((u & 0x80000000u) ? (u & 0x7fffffffu) : ~u);
}

__device__ __forceinline__ uint32_t rank_of(uint32_t key) {
    uint32_t g = key >> 7;
    uint4 bm = reinterpret_cast<const uint4*>(g_bitmap)[g];
    uint32_t widx = (key >> 5) & 3u, pos = key & 31u;
    uint32_t below = 0;
    if (widx > 0) below += __popc(bm.x);
    if (widx > 1) below += __popc(bm.y);
    if (widx > 2) below += __popc(bm.z);
    uint32_t w = (widx == 0) ? bm.x : (widx == 1) ? bm.y : (widx == 2) ? bm.z : bm.w;
    below += __popc(w & ((1u << pos) - 1u));
    return g_blkoff[g >> 8] + g_gprefix[g] + below;
}

// K1: reset counters, pack key, set bitmap bit; dup flag -> key bit31.
__global__ void k1_build(const int* __restrict__ coords, int n, int half) {
    int t = blockIdx.x * blockDim.x + threadIdx.x;
    if (t == 0) { g_ndup = 0u; g_nrank = 0u; }
    #pragma unroll
    for (int q = 0; q < 2; ++q) {
        int i = t + q * half;
        if (t >= half || i >= n) break;
        int4 c = reinterpret_cast<const int4*>(coords)[i];
        uint32_t key = ((uint32_t)c.x << 21) | ((uint32_t)(c.y >> 1) << 14) |
                       ((uint32_t)(c.z >> 1) << 7) | ((uint32_t)(c.w >> 1));
        uint32_t bit = 1u << (key & 31u);
        uint32_t old = atomicOr(&g_bitmap[key >> 5], bit);
        g_keys[i] = key | ((old & bit) ? 0x80000000u : 0u);
    }
}

// K2a: per-group popcount + intra-block exclusive scan; emit block totals.
__global__ void k2a_scan(void) {
    __shared__ uint32_t warpsum[8];
    uint32_t t = threadIdx.x;
    uint32_t gid = blockIdx.x * 256u + t;
    uint4 v = reinterpret_cast<const uint4*>(g_bitmap)[gid];
    uint32_t p = __popc(v.x) + __popc(v.y) + __popc(v.z) + __popc(v.w);
    uint32_t lane = t & 31u, wid = t >> 5;
    uint32_t x = p;
    #pragma unroll
    for (int o = 1; o < 32; o <<= 1) {
        uint32_t y = __shfl_up_sync(0xffffffffu, x, o);
        if (lane >= (uint32_t)o) x += y;
    }
    if (lane == 31) warpsum[wid] = x;
    __syncthreads();
    if (wid == 0) {
        uint32_t w = (lane < 8) ? warpsum[lane] : 0u;
        #pragma unroll
        for (int o = 1; o < 8; o <<= 1) {
            uint32_t y = __shfl_up_sync(0xffffffffu, w, o);
            if (lane >= (uint32_t)o) w += y;
        }
        if (lane < 8) warpsum[lane] = w;
    }
    __syncthreads();
    uint32_t excl = x - p + (wid ? warpsum[wid - 1] : 0u);
    g_gprefix[gid] = excl;
    if (t == 255) g_blksum[blockIdx.x] = excl + p;
}

// K2b: single-block (1024 thr) exclusive scan of 16384 block sums.
__global__ void k2b_scan(void) {
    __shared__ uint32_t warpsum[32];
    uint32_t t = threadIdx.x;
    uint32_t s[16];
    #pragma unroll
    for (int q = 0; q < 4; ++q) {
        uint4 v = reinterpret_cast<const uint4*>(g_blksum)[t * 4u + q];
        s[q * 4 + 0] = v.x; s[q * 4 + 1] = v.y; s[q * 4 + 2] = v.z; s[q * 4 + 3] = v.w;
    }
    uint32_t local = 0;
    #pragma unroll
    for (int j = 0; j < 16; ++j) local += s[j];
    uint32_t lane = t & 31u, wid = t >> 5;
    uint32_t x = local;
    #pragma unroll
    for (int o = 1; o < 32; o <<= 1) {
        uint32_t y = __shfl_up_sync(0xffffffffu, x, o);
        if (lane >= (uint32_t)o) x += y;
    }
    if (lane == 31) warpsum[wid] = x;
    __syncthreads();
    if (wid == 0) {
        uint32_t w = warpsum[lane];
        #pragma unroll
        for (int o = 1; o < 32; o <<= 1) {
            uint32_t y = __shfl_up_sync(0xffffffffu, w, o);
            if (lane >= (uint32_t)o) w += y;
        }
        warpsum[lane] = w;
    }
    __syncthreads();
    uint32_t run = x - local + (wid ? warpsum[wid - 1] : 0u);
    #pragma unroll
    for (int j = 0; j < 16; ++j) {
        g_blkoff[t * 16u + j] = run;
        run += s[j];
    }
    if (t == 1023) g_numuniq = run;
}

// K5: pure ranking, 2 inputs per thread, simple form (measured-best).
__device__ __forceinline__ void rank_one(int i) {
    uint32_t kf = g_keys[i];
    uint32_t rank = rank_of(kf & KEYMASK);
    bool dup = (kf & 0x80000000u) != 0u;
    g_inv[i] = rank | (dup ? 0x80000000u : 0u);
    if (dup) {
        uint32_t d = atomicAdd(&g_ndup, 1u);
        if (d < DUP_CAP) g_duplist[d] = (uint32_t)i;
        if (atomicCAS(&g_cid[rank], 0u, 1u) == 0u) {
            uint32_t rt = atomicAdd(&g_nrank, 1u);
            if (rt < COLL_CAP) g_ranklist[rt] = rank;
        }
    }
}

__global__ void __launch_bounds__(256) k5_rank(int n, int half) {
    int t = blockIdx.x * blockDim.x + threadIdx.x;
    if (t < half) rank_one(t);
    int i2 = t + half;
    if (t < half && i2 < n) rank_one(i2);
}

// pts/cnt scatter for one non-dup input (used by k67 pts partition).
__device__ __forceinline__ void pts_one(int i,
                                        const float* __restrict__ points,
                                        const float* __restrict__ count,
                                        float* __restrict__ out, int n) {
    uint32_t iv = g_inv[i];
    if (iv & 0x80000000u) return;
    float c = count[i];
    float3 p = *reinterpret_cast<const float3*>(points + (size_t)i * 3);
    float* op = out + (size_t)n * 96 + (size_t)iv * 3;
    bool v = c > 0.f;
    __stcs(op + 0, v ? p.x : c * p.x);
    __stcs(op + 1, v ? p.y : c * p.y);
    __stcs(op + 2, v ? p.z : c * p.z);
    __stcs(out + (size_t)n * 99 + iv, c);
}

// K67: one launch, three block partitions, all depending only on k5.
//   blocks [0, P)          : pts/cnt scatter (thread per input, 2-way)
//   blocks [P, P+ZBLOCKS)  : streaming-zero the bitmap (grid-stride uint4)
//   blocks [P+ZBLOCKS, ..) : feats stream (thread per float4, 2-way split-half)
__global__ void k67_main(const float* __restrict__ feats,
                         const float* __restrict__ points,
                         const float* __restrict__ count,
                         float* __restrict__ out, int n,
                         int halfn, unsigned P, unsigned half) {
    unsigned bid = blockIdx.x;
    if (bid < P) {
        int t = bid * blockDim.x + threadIdx.x;
        if (t < halfn) {
            pts_one(t, points, count, out, n);
            int i2 = t + halfn;
            if (i2 < n) pts_one(i2, points, count, out, n);
        }
        return;
    }
    if (bid < P + ZBLOCKS) {
        uint32_t idx = (bid - P) * blockDim.x + threadIdx.x;
        uint4 z = make_uint4(0u, 0u, 0u, 0u);
        for (uint32_t w = idx; w < NWORDS / 4; w += ZBLOCKS * 256u)
            reinterpret_cast<uint4*>(g_bitmap)[w] = z;
        return;
    }
    unsigned t = (bid - P - ZBLOCKS) * blockDim.x + threadIdx.x;
    unsigned total = (unsigned)n * 24u;
    #pragma unroll
    for (int q = 0; q < 2; ++q) {
        unsigned f = t + (unsigned)q * half;
        if (f >= total || (q == 1 && t >= half)) break;
        unsigned i = f / 24u, c = f % 24u;
        uint32_t iv = g_inv[i];
        if (iv & 0x80000000u) continue;
        float cnt = count[i];
        float4 v = __ldcs(reinterpret_cast<const float4*>(feats) + f);
        if (!(cnt > 0.f)) v = make_float4(0.f, 0.f, 0.f, 0.f);
        __stcs(reinterpret_cast<float4*>(out) + (size_t)iv * 24u + c, v);
    }
}

// FixA: per collided rank — encode first-inserter feats row in place;
//       pts -> raw sum form (p0 -> c0*p0 when c0>0).
__global__ void kfa(float* __restrict__ out, int n) {
    uint32_t nr = g_nrank;
    uint32_t warp = blockIdx.x * (blockDim.x >> 5) + (threadIdx.x >> 5);
    uint32_t nwarps = gridDim.x * (blockDim.x >> 5);
    int lane = threadIdx.x & 31;
    for (uint32_t t = warp; t < nr; t += nwarps) {
        uint32_t r = g_ranklist[t];
        if (lane < 24) {
            float4 v = reinterpret_cast<const float4*>(out)[(size_t)r * 24 + lane];
            uint4 e = make_uint4(encf(v.x), encf(v.y), encf(v.z), encf(v.w));
            reinterpret_cast<uint4*>(out)[(size_t)r * 24 + lane] = e;
        } else if (lane == 24) {
            float c0 = out[(size_t)n * 99 + r];
            if (c0 > 0.f) {
                float* op = out + (size_t)n * 96 + (size_t)r * 3;
                op[0] *= c0; op[1] *= c0; op[2] *= c0;
            }
        }
    }
}

// FixB: per dup input — encoded atomicMax into out feats; atomicAdd pts/cnt.
__global__ void kfb(const float* __restrict__ feats,
                    const float* __restrict__ points,
                    const float* __restrict__ count,
                    float* __restrict__ out, int n) {
    uint32_t nd = g_ndup;
    uint32_t warp = blockIdx.x * (blockDim.x >> 5) + (threadIdx.x >> 5);
    uint32_t nwarps = gridDim.x * (blockDim.x >> 5);
    int lane = threadIdx.x & 31;
    for (uint32_t t = warp; t < nd; t += nwarps) {
        uint32_t i = g_duplist[t];
        uint32_t rank = g_inv[i] & 0x7fffffffu;
        if (lane < 24) {
            float4 v = reinterpret_cast<const float4*>(feats)[(size_t)i * 24 + lane];
            uint32_t* o = reinterpret_cast<uint32_t*>(out) + (size_t)rank * 96 + lane * 4;
            atomicMax(o + 0, encf(v.x));
            atomicMax(o + 1, encf(v.y));
            atomicMax(o + 2, encf(v.z));
            atomicMax(o + 3, encf(v.w));
        } else if (lane < 27) {
            float c = count[i];
            float p = points[(size_t)i * 3 + (lane - 24)];
            atomicAdd(out + (size_t)n * 96 + (size_t)rank * 3 + (lane - 24), c * p);
        } else if (lane == 27) {
            atomicAdd(out + (size_t)n * 99 + rank, count[i]);
        }
    }
}

// FixC: blocks 0..31: decode collided rows, divide centroids, clean cid.
//       blocks 32..39: zero empty tail rows [U, n).
__global__ void kfc(float* __restrict__ out, int n) {
    int lane = threadIdx.x & 31;
    if (blockIdx.x < 32) {
        uint32_t nr = g_nrank;
        uint32_t warp = blockIdx.x * (blockDim.x >> 5) + (threadIdx.x >> 5);
        uint32_t nwarps = 32 * (blockDim.x >> 5);
        for (uint32_t t = warp; t < nr; t += nwarps) {
            uint32_t r = g_ranklist[t];
            float cnt = out[(size_t)n * 99 + r];
            bool valid = cnt > 0.f;
            float div = valid ? cnt : 1.f;
            if (lane < 24) {
                uint4 e = reinterpret_cast<const uint4*>(out)[(size_t)r * 24 + lane];
                float4 d = valid ? make_float4(decf(e.x), decf(e.y), decf(e.z), decf(e.w))
                                 : make_float4(0.f, 0.f, 0.f, 0.f);
                reinterpret_cast<float4*>(out)[(size_t)r * 24 + lane] = d;
            } else if (lane == 24) {
                float* op = out + (size_t)n * 96 + (size_t)r * 3;
                op[0] /= div; op[1] /= div; op[2] /= div;
            } else if (lane == 25) {
                g_cid[r] = 0u;
            }
        }
    } else {
        uint32_t U = g_numuniq;
        uint32_t warp = (blockIdx.x - 32) * (blockDim.x >> 5) + (threadIdx.x >> 5);
        uint32_t nwarps = 8 * (blockDim.x >> 5);
        for (uint32_t r = U + warp; r < (uint32_t)n; r += nwarps) {
            if (lane < 24)
                reinterpret_cast<float4*>(out)[(size_t)r * 24 + lane] =
                    make_float4(0.f, 0.f, 0.f, 0.f);
            else if (lane < 27)
                out[(size_t)n * 96 + (size_t)r * 3 + (lane - 24)] = 0.f;
            else if (lane == 27)
                out[(size_t)n * 99 + r] = 0.f;
        }
    }
}

extern "C" void kernel_launch(void* const* d_in, const int* in_sizes, int n_in,
                              void* d_out, int out_size) {
    const int*   coords = (const int*)d_in[0];
    const float* feats  = (const float*)d_in[1];
    const float* points = (const float*)d_in[2];
    const float* count  = (const float*)d_in[3];
    int n = in_sizes[3];
    float* out = (float*)d_out;

    const int TB = 256;
    int halfn = (n + 1) / 2;
    k1_build<<<(halfn + TB - 1) / TB, TB>>>(coords, n, halfn);
    k2a_scan<<<NSCANBLK, 256>>>();
    k2b_scan<<<1, 1024>>>();
    k5_rank<<<(halfn + TB - 1) / TB, TB>>>(n, halfn);

    unsigned total = (unsigned)n * 24u;
    unsigned half = (total + 1u) / 2u;
    unsigned P = (unsigned)((halfn + TB - 1) / TB);
    unsigned F = (half + TB - 1u) / (unsigned)TB;
    k67_main<<<P + ZBLOCKS + F, TB>>>(feats, points, count, out, n,
                                      halfn, P, half);
    kfa<<<32, 256>>>(out, n);
    kfb<<<64, 256>>>(feats, points, count, out, n);
    kfc<<<40, 256>>>(out, n);
}

// round 17
// speedup vs baseline: 1.2003x; 1.2003x over previous
#include <cuda_runtime.h>
#include <cuda_bf16.h>
#include <cstdint>

#define MAXN (1 << 21)            // >= N = 1,000,000
#define NBITS (1u << 29)          // keyspace: 8b batch | 7b x | 7b y | 7b z
#define NWORDS (NBITS / 32u)      // 16M u32 = 64MB
#define NGROUPS (NBITS / 128u)    // 4M groups of 128 bits
#define NSCANBLK (NGROUPS / 256u) // 16384 pass-1 blocks
#define COLL_CAP 32768
#define DUP_CAP  65536
#define KEYMASK 0x1fffffffu

__device__ uint32_t g_bitmap[NWORDS];   // all-zero between calls (kfc cleans)
__device__ uint32_t g_gprefix[NGROUPS];
__device__ uint32_t g_blksum[NSCANBLK];
__device__ uint32_t g_blkoff[NSCANBLK];
__device__ uint32_t g_numuniq;
__device__ uint32_t g_keys[MAXN];       // bit31 = "2nd+ inserter of its key"
__device__ uint32_t g_inv[MAXN];        // bit31 = dup flag, low = rank
__device__ uint32_t g_cid[MAXN];        // claim flag per rank; 0 between calls
__device__ uint32_t g_duplist[DUP_CAP];
__device__ uint32_t g_ranklist[COLL_CAP];
__device__ uint32_t g_ndup, g_nrank;

__device__ __forceinline__ uint32_t encf(float f) {
    uint32_t b = __float_as_uint(f);
    return (b & 0x80000000u) ? ~b : (b | 0x80000000u);
}
__device__ __forceinline__ float decf(uint32_t u) {
    return __uint_as_float((u & 0x80000000u) ? (u & 0x7fffffffu) : ~u);
}

__device__ __forceinline__ uint32_t rank_of(uint32_t key) {
    uint32_t g = key >> 7;
    uint4 bm = reinterpret_cast<const uint4*>(g_bitmap)[g];
    uint32_t widx = (key >> 5) & 3u, pos = key & 31u;
    uint32_t below = 0;
    if (widx > 0) below += __popc(bm.x);
    if (widx > 1) below += __popc(bm.y);
    if (widx > 2) below += __popc(bm.z);
    uint32_t w = (widx == 0) ? bm.x : (widx == 1) ? bm.y : (widx == 2) ? bm.z : bm.w;
    below += __popc(w & ((1u << pos) - 1u));
    return g_blkoff[g >> 8] + g_gprefix[g] + below;
}

// K1: reset counters, pack key, set bitmap bit; dup flag -> key bit31.
__global__ void k1_build(const int* __restrict__ coords, int n, int half) {
    int t = blockIdx.x * blockDim.x + threadIdx.x;
    if (t == 0) { g_ndup = 0u; g_nrank = 0u; }
    #pragma unroll
    for (int q = 0; q < 2; ++q) {
        int i = t + q * half;
        if (t >= half || i >= n) break;
        int4 c = reinterpret_cast<const int4*>(coords)[i];
        uint32_t key = ((uint32_t)c.x << 21) | ((uint32_t)(c.y >> 1) << 14) |
                       ((uint32_t)(c.z >> 1) << 7) | ((uint32_t)(c.w >> 1));
        uint32_t bit = 1u << (key & 31u);
        uint32_t old = atomicOr(&g_bitmap[key >> 5], bit);
        g_keys[i] = key | ((old & bit) ? 0x80000000u : 0u);
    }
}

// K2a: per-group popcount + intra-block exclusive scan; emit block totals.
__global__ void k2a_scan(void) {
    __shared__ uint32_t warpsum[8];
    uint32_t t = threadIdx.x;
    uint32_t gid = blockIdx.x * 256u + t;
    uint4 v = reinterpret_cast<const uint4*>(g_bitmap)[gid];
    uint32_t p = __popc(v.x) + __popc(v.y) + __popc(v.z) + __popc(v.w);
    uint32_t lane = t & 31u, wid = t >> 5;
    uint32_t x = p;
    #pragma unroll
    for (int o = 1; o < 32; o <<= 1) {
        uint32_t y = __shfl_up_sync(0xffffffffu, x, o);
        if (lane >= (uint32_t)o) x += y;
    }
    if (lane == 31) warpsum[wid] = x;
    __syncthreads();
    if (wid == 0) {
        uint32_t w = (lane < 8) ? warpsum[lane] : 0u;
        #pragma unroll
        for (int o = 1; o < 8; o <<= 1) {
            uint32_t y = __shfl_up_sync(0xffffffffu, w, o);
            if (lane >= (uint32_t)o) w += y;
        }
        if (lane < 8) warpsum[lane] = w;
    }
    __syncthreads();
    uint32_t excl = x - p + (wid ? warpsum[wid - 1] : 0u);
    g_gprefix[gid] = excl;
    if (t == 255) g_blksum[blockIdx.x] = excl + p;
}

// K2b: single-block (1024 thr) exclusive scan of 16384 block sums.
__global__ void k2b_scan(void) {
    __shared__ uint32_t warpsum[32];
    uint32_t t = threadIdx.x;
    uint32_t s[16];
    #pragma unroll
    for (int q = 0; q < 4; ++q) {
        uint4 v = reinterpret_cast<const uint4*>(g_blksum)[t * 4u + q];
        s[q * 4 + 0] = v.x; s[q * 4 + 1] = v.y; s[q * 4 + 2] = v.z; s[q * 4 + 3] = v.w;
    }
    uint32_t local = 0;
    #pragma unroll
    for (int j = 0; j < 16; ++j) local += s[j];
    uint32_t lane = t & 31u, wid = t >> 5;
    uint32_t x = local;
    #pragma unroll
    for (int o = 1; o < 32; o <<= 1) {
        uint32_t y = __shfl_up_sync(0xffffffffu, x, o);
        if (lane >= (uint32_t)o) x += y;
    }
    if (lane == 31) warpsum[wid] = x;
    __syncthreads();
    if (wid == 0) {
        uint32_t w = warpsum[lane];
        #pragma unroll
        for (int o = 1; o < 32; o <<= 1) {
            uint32_t y = __shfl_up_sync(0xffffffffu, w, o);
            if (lane >= (uint32_t)o) w += y;
        }
        warpsum[lane] = w;
    }
    __syncthreads();
    uint32_t run = x - local + (wid ? warpsum[wid - 1] : 0u);
    #pragma unroll
    for (int j = 0; j < 16; ++j) {
        g_blkoff[t * 16u + j] = run;
        run += s[j];
    }
    if (t == 1023) g_numuniq = run;
}

// K5: pure ranking, 2 inputs per thread, simple form (measured-best).
__device__ __forceinline__ void rank_one(int i) {
    uint32_t kf = g_keys[i];
    uint32_t rank = rank_of(kf & KEYMASK);
    bool dup = (kf & 0x80000000u) != 0u;
    g_inv[i] = rank | (dup ? 0x80000000u : 0u);
    if (dup) {
        uint32_t d = atomicAdd(&g_ndup, 1u);
        if (d < DUP_CAP) g_duplist[d] = (uint32_t)i;
        if (atomicCAS(&g_cid[rank], 0u, 1u) == 0u) {
            uint32_t rt = atomicAdd(&g_nrank, 1u);
            if (rt < COLL_CAP) g_ranklist[rt] = rank;
        }
    }
}

__global__ void __launch_bounds__(256) k5_rank(int n, int half) {
    int t = blockIdx.x * blockDim.x + threadIdx.x;
    if (t < half) rank_one(t);
    int i2 = t + half;
    if (t < half && i2 < n) rank_one(i2);
}

// K6: pts/cnt scatter for non-dup inputs. Thread per input, 2-way split-half.
__device__ __forceinline__ void pts_one(int i,
                                        const float* __restrict__ points,
                                        const float* __restrict__ count,
                                        float* __restrict__ out, int n) {
    uint32_t iv = g_inv[i];
    if (iv & 0x80000000u) return;
    float c = count[i];
    float3 p = *reinterpret_cast<const float3*>(points + (size_t)i * 3);
    float* op = out + (size_t)n * 96 + (size_t)iv * 3;
    bool v = c > 0.f;
    __stcs(op + 0, v ? p.x : c * p.x);
    __stcs(op + 1, v ? p.y : c * p.y);
    __stcs(op + 2, v ? p.z : c * p.z);
    __stcs(out + (size_t)n * 99 + iv, c);
}

__global__ void __launch_bounds__(256) k6_pts(const float* __restrict__ points,
                        const float* __restrict__ count,
                        float* __restrict__ out, int n, int half) {
    int t = blockIdx.x * blockDim.x + threadIdx.x;
    if (t < half) pts_one(t, points, count, out, n);
    int i2 = t + half;
    if (t < half && i2 < n) pts_one(i2, points, count, out, n);
}

// K7: pure feats stream. Thread per float4, 4 per thread (quarter-split,
//     batched loads -> 4 independent chains; R11-measured ~5us better).
__global__ void k7_feats(const float* __restrict__ feats,
                         const float* __restrict__ count,
                         float* __restrict__ out, int n, unsigned quarter) {
    unsigned t = blockIdx.x * blockDim.x + threadIdx.x;
    if (t >= quarter) return;
    unsigned total = (unsigned)n * 24u;

    unsigned f[4]; unsigned iw[4]; unsigned cc[4]; int m = 0;
    #pragma unroll
    for (int q = 0; q < 4; ++q) {
        unsigned ff = t + (unsigned)q * quarter;
        if (ff < total) { f[m] = ff; iw[m] = ff / 24u; cc[m] = ff % 24u; ++m; }
    }
    uint32_t iv[4]; float cnt[4];
    #pragma unroll
    for (int q = 0; q < 4; ++q) {
        if (q >= m) break;
        iv[q] = g_inv[iw[q]];
        cnt[q] = count[iw[q]];
    }
    float4 v[4];
    #pragma unroll
    for (int q = 0; q < 4; ++q) {
        if (q >= m) break;
        v[q] = __ldcs(reinterpret_cast<const float4*>(feats) + f[q]);
    }
    #pragma unroll
    for (int q = 0; q < 4; ++q) {
        if (q >= m) break;
        if (iv[q] & 0x80000000u) continue;
        float4 w = v[q];
        if (!(cnt[q] > 0.f)) w = make_float4(0.f, 0.f, 0.f, 0.f);
        __stcs(reinterpret_cast<float4*>(out) + (size_t)iv[q] * 24u + cc[q], w);
    }
}

// FixA: per collided rank — encode first-inserter feats row in place;
//       pts -> raw sum form (p0 -> c0*p0 when c0>0).
__global__ void kfa(float* __restrict__ out, int n) {
    uint32_t nr = g_nrank;
    uint32_t warp = blockIdx.x * (blockDim.x >> 5) + (threadIdx.x >> 5);
    uint32_t nwarps = gridDim.x * (blockDim.x >> 5);
    int lane = threadIdx.x & 31;
    for (uint32_t t = warp; t < nr; t += nwarps) {
        uint32_t r = g_ranklist[t];
        if (lane < 24) {
            float4 v = reinterpret_cast<const float4*>(out)[(size_t)r * 24 + lane];
            uint4 e = make_uint4(encf(v.x), encf(v.y), encf(v.z), encf(v.w));
            reinterpret_cast<uint4*>(out)[(size_t)r * 24 + lane] = e;
        } else if (lane == 24) {
            float c0 = out[(size_t)n * 99 + r];
            if (c0 > 0.f) {
                float* op = out + (size_t)n * 96 + (size_t)r * 3;
                op[0] *= c0; op[1] *= c0; op[2] *= c0;
            }
        }
    }
}

// FixB: per dup input — encoded atomicMax into out feats; atomicAdd pts/cnt.
__global__ void kfb(const float* __restrict__ feats,
                    const float* __restrict__ points,
                    const float* __restrict__ count,
                    float* __restrict__ out, int n) {
    uint32_t nd = g_ndup;
    uint32_t warp = blockIdx.x * (blockDim.x >> 5) + (threadIdx.x >> 5);
    uint32_t nwarps = gridDim.x * (blockDim.x >> 5);
    int lane = threadIdx.x & 31;
    for (uint32_t t = warp; t < nd; t += nwarps) {
        uint32_t i = g_duplist[t];
        uint32_t rank = g_inv[i] & 0x7fffffffu;
        if (lane < 24) {
            float4 v = reinterpret_cast<const float4*>(feats)[(size_t)i * 24 + lane];
            uint32_t* o = reinterpret_cast<uint32_t*>(out) + (size_t)rank * 96 + lane * 4;
            atomicMax(o + 0, encf(v.x));
            atomicMax(o + 1, encf(v.y));
            atomicMax(o + 2, encf(v.z));
            atomicMax(o + 3, encf(v.w));
        } else if (lane < 27) {
            float c = count[i];
            float p = points[(size_t)i * 3 + (lane - 24)];
            atomicAdd(out + (size_t)n * 96 + (size_t)rank * 3 + (lane - 24), c * p);
        } else if (lane == 27) {
            atomicAdd(out + (size_t)n * 99 + rank, count[i]);
        }
    }
}

// FixC: blocks 0..31: decode collided rows, divide centroids, clean cid.
//       blocks 32..39: zero empty tail rows [U, n).
//       blocks 40..  : streaming-zero the bitmap.
__global__ void kfc(float* __restrict__ out, int n) {
    int lane = threadIdx.x & 31;
    if (blockIdx.x < 32) {
        uint32_t nr = g_nrank;
        uint32_t warp = blockIdx.x * (blockDim.x >> 5) + (threadIdx.x >> 5);
        uint32_t nwarps = 32 * (blockDim.x >> 5);
        for (uint32_t t = warp; t < nr; t += nwarps) {
            uint32_t r = g_ranklist[t];
            float cnt = out[(size_t)n * 99 + r];
            bool valid = cnt > 0.f;
            float div = valid ? cnt : 1.f;
            if (lane < 24) {
                uint4 e = reinterpret_cast<const uint4*>(out)[(size_t)r * 24 + lane];
                float4 d = valid ? make_float4(decf(e.x), decf(e.y), decf(e.z), decf(e.w))
                                 : make_float4(0.f, 0.f, 0.f, 0.f);
                reinterpret_cast<float4*>(out)[(size_t)r * 24 + lane] = d;
            } else if (lane == 24) {
                float* op = out + (size_t)n * 96 + (size_t)r * 3;
                op[0] /= div; op[1] /= div; op[2] /= div;
            } else if (lane == 25) {
                g_cid[r] = 0u;
            }
        }
    } else if (blockIdx.x < 40) {
        uint32_t U = g_numuniq;
        uint32_t warp = (blockIdx.x - 32) * (blockDim.x >> 5) + (threadIdx.x >> 5);
        uint32_t nwarps = 8 * (blockDim.x >> 5);
        for (uint32_t r = U + warp; r < (uint32_t)n; r += nwarps) {
            if (lane < 24)
                reinterpret_cast<float4*>(out)[(size_t)r * 24 + lane] =
                    make_float4(0.f, 0.f, 0.f, 0.f);
            else if (lane < 27)
                out[(size_t)n * 96 + (size_t)r * 3 + (lane - 24)] = 0.f;
            else if (lane == 27)
                out[(size_t)n * 99 + r] = 0.f;
        }
    } else {
        uint32_t idx = (blockIdx.x - 40) * blockDim.x + threadIdx.x;
        uint32_t stride = (gridDim.x - 40) * blockDim.x;
        uint4 z = make_uint4(0u, 0u, 0u, 0u);
        for (uint32_t w = idx; w < NWORDS / 4; w += stride)
            reinterpret_cast<uint4*>(g_bitmap)[w] = z;
    }
}

extern "C" void kernel_launch(void* const* d_in, const int* in_sizes, int n_in,
                              void* d_out, int out_size) {
    const int*   coords = (const int*)d_in[0];
    const float* feats  = (const float*)d_in[1];
    const float* points = (const float*)d_in[2];
    const float* count  = (const float*)d_in[3];
    int n = in_sizes[3];
    float* out = (float*)d_out;

    const int TB = 256;
    int halfn = (n + 1) / 2;
    k1_build<<<(halfn + TB - 1) / TB, TB>>>(coords, n, halfn);
    k2a_scan<<<NSCANBLK, 256>>>();
    k2b_scan<<<1, 1024>>>();
    k5_rank<<<(halfn + TB - 1) / TB, TB>>>(n, halfn);
    k6_pts<<<(halfn + TB - 1) / TB, TB>>>(points, count, out, n, halfn);
    unsigned total = (unsigned)n * 24u;
    unsigned quarter = (total + 3u) / 4u;
    k7_feats<<<(quarter + TB - 1) / TB, TB>>>(feats, count, out, n, quarter);
    kfa<<<32, 256>>>(out, n);
    kfb<<<64, 256>>>(feats, points, count, out, n);
    kfc<<<592, 256>>>(out, n);
}